// round 5
// baseline (speedup 1.0000x reference)
#include <cuda_runtime.h>
#include <math.h>

#define BB 2
#define SS 2048
#define DD 4096
#define QKVN 6144
#define HKV 8
#define NH 32
#define HD 128

// ---------------- scratch (static device globals; no runtime allocation) ----------------
__device__ float g_qkv[(size_t)BB * SS * QKVN];        // 100.7 MB
__device__ float g_q[(size_t)BB * NH * SS * HD];       // 67 MB
__device__ float g_k[(size_t)BB * HKV * SS * HD];      // 16.8 MB
__device__ float g_v[(size_t)BB * HKV * SS * HD];      // 16.8 MB
__device__ float g_scores[(size_t)BB * NH * SS * SS];  // 1.07 GB
__device__ float g_attn[(size_t)BB * SS * DD];         // 67 MB

// ---------------- generic fp32 GEMM, C = alpha * A * B^T (both operands K-major) --------
// Tile 128x128, BK=8, 256 threads, 8x8 register tile per thread.
// bgqa: B operand indexed per-KV-head (GQA): batch z = b*32+h -> B batch (b*8 + h/4)
// cmode: 1 -> C written into [B, S, 32, HD] layout at (b = z>>5, h = z&31)
__global__ __launch_bounds__(256) void gemm_nt(
    const float* __restrict__ Ag, const float* __restrict__ Bg, float* __restrict__ Cg,
    int K, int lda, int ldb, int ldc,
    long long sA, long long sB, long long sC, float alpha, int bgqa, int cmode)
{
    int z = blockIdx.z;
    const float* A = Ag + (long long)z * sA;
    const float* Bp = Bg + (bgqa ? (long long)((z >> 5) * HKV + ((z & 31) >> 2)) * sB
                                 : (long long)z * sB);
    float* C = Cg + (cmode ? (long long)(z >> 5) * SS * DD + (long long)(z & 31) * HD
                           : (long long)z * sC);

    __shared__ __align__(16) float Asm[8][128];
    __shared__ __align__(16) float Bsm[8][128];

    int tid = threadIdx.x;
    int tx = tid & 15, ty = tid >> 4;
    int lr = tid >> 1;          // 0..127
    int kq = (tid & 1) * 4;     // 0 or 4

    const float* aPtr = A + (long long)(blockIdx.y * 128 + lr) * lda + kq;
    const float* bPtr = Bp + (long long)(blockIdx.x * 128 + lr) * ldb + kq;

    float acc[8][8];
#pragma unroll
    for (int i = 0; i < 8; i++)
#pragma unroll
        for (int j = 0; j < 8; j++) acc[i][j] = 0.0f;

    for (int k0 = 0; k0 < K; k0 += 8) {
        float4 a4 = *(const float4*)(aPtr + k0);
        float4 b4 = *(const float4*)(bPtr + k0);
        __syncthreads();
        Asm[kq + 0][lr] = a4.x; Asm[kq + 1][lr] = a4.y;
        Asm[kq + 2][lr] = a4.z; Asm[kq + 3][lr] = a4.w;
        Bsm[kq + 0][lr] = b4.x; Bsm[kq + 1][lr] = b4.y;
        Bsm[kq + 2][lr] = b4.z; Bsm[kq + 3][lr] = b4.w;
        __syncthreads();
#pragma unroll
        for (int kk = 0; kk < 8; kk++) {
            float a[8], b[8];
            *(float4*)&a[0] = *(const float4*)&Asm[kk][ty * 4];
            *(float4*)&a[4] = *(const float4*)&Asm[kk][64 + ty * 4];
            *(float4*)&b[0] = *(const float4*)&Bsm[kk][tx * 4];
            *(float4*)&b[4] = *(const float4*)&Bsm[kk][64 + tx * 4];
#pragma unroll
            for (int i = 0; i < 8; i++)
#pragma unroll
                for (int j = 0; j < 8; j++)
                    acc[i][j] += a[i] * b[j];
        }
    }

#pragma unroll
    for (int i = 0; i < 8; i++) {
        int r = blockIdx.y * 128 + ty * 4 + (i & 3) + ((i >> 2) << 6);
        float4 c0 = make_float4(acc[i][0] * alpha, acc[i][1] * alpha,
                                acc[i][2] * alpha, acc[i][3] * alpha);
        float4 c1 = make_float4(acc[i][4] * alpha, acc[i][5] * alpha,
                                acc[i][6] * alpha, acc[i][7] * alpha);
        *(float4*)(C + (long long)r * ldc + blockIdx.x * 128 + tx * 4) = c0;
        *(float4*)(C + (long long)r * ldc + blockIdx.x * 128 + 64 + tx * 4) = c1;
    }
}

// ---------------- generic fp32 GEMM, C = A * B (A K-major, B [K,N] N-major) -------------
__global__ __launch_bounds__(256) void gemm_nn(
    const float* __restrict__ Ag, const float* __restrict__ Bg, float* __restrict__ Cg,
    int K, int lda, int ldb, int ldc,
    long long sA, long long sB, long long sC, float alpha, int bgqa, int cmode)
{
    int z = blockIdx.z;
    const float* A = Ag + (long long)z * sA;
    const float* Bp = Bg + (bgqa ? (long long)((z >> 5) * HKV + ((z & 31) >> 2)) * sB
                                 : (long long)z * sB);
    float* C = Cg + (cmode ? (long long)(z >> 5) * SS * DD + (long long)(z & 31) * HD
                           : (long long)z * sC);

    __shared__ __align__(16) float Asm[8][128];
    __shared__ __align__(16) float Bsm[8][128];

    int tid = threadIdx.x;
    int tx = tid & 15, ty = tid >> 4;
    int lr = tid >> 1;
    int kq = (tid & 1) * 4;
    int bk = tid >> 5;            // 0..7
    int bn = (tid & 31) * 4;      // 0..124

    const float* aPtr = A + (long long)(blockIdx.y * 128 + lr) * lda + kq;
    const float* bPtr = Bp + (long long)bk * ldb + blockIdx.x * 128 + bn;

    float acc[8][8];
#pragma unroll
    for (int i = 0; i < 8; i++)
#pragma unroll
        for (int j = 0; j < 8; j++) acc[i][j] = 0.0f;

    for (int k0 = 0; k0 < K; k0 += 8) {
        float4 a4 = *(const float4*)(aPtr + k0);
        float4 b4 = *(const float4*)(bPtr + (long long)k0 * ldb);
        __syncthreads();
        Asm[kq + 0][lr] = a4.x; Asm[kq + 1][lr] = a4.y;
        Asm[kq + 2][lr] = a4.z; Asm[kq + 3][lr] = a4.w;
        *(float4*)&Bsm[bk][bn] = b4;
        __syncthreads();
#pragma unroll
        for (int kk = 0; kk < 8; kk++) {
            float a[8], b[8];
            *(float4*)&a[0] = *(const float4*)&Asm[kk][ty * 4];
            *(float4*)&a[4] = *(const float4*)&Asm[kk][64 + ty * 4];
            *(float4*)&b[0] = *(const float4*)&Bsm[kk][tx * 4];
            *(float4*)&b[4] = *(const float4*)&Bsm[kk][64 + tx * 4];
#pragma unroll
            for (int i = 0; i < 8; i++)
#pragma unroll
                for (int j = 0; j < 8; j++)
                    acc[i][j] += a[i] * b[j];
        }
    }

#pragma unroll
    for (int i = 0; i < 8; i++) {
        int r = blockIdx.y * 128 + ty * 4 + (i & 3) + ((i >> 2) << 6);
        float4 c0 = make_float4(acc[i][0] * alpha, acc[i][1] * alpha,
                                acc[i][2] * alpha, acc[i][3] * alpha);
        float4 c1 = make_float4(acc[i][4] * alpha, acc[i][5] * alpha,
                                acc[i][6] * alpha, acc[i][7] * alpha);
        *(float4*)(C + (long long)r * ldc + blockIdx.x * 128 + tx * 4) = c0;
        *(float4*)(C + (long long)r * ldc + blockIdx.x * 128 + 64 + tx * 4) = c1;
    }
}

// ---------------- RoPE + RMSNorm + QKV split ----------------
// grid: (48 head-slots, S, B), block: 128 (one thread per dim)
// slot layout in qkv row: hh = kv*6 + slot; slot 0..3 = q heads, 4 = k, 5 = v
__global__ __launch_bounds__(128) void rope_norm_kernel(
    const float* __restrict__ cosp, const float* __restrict__ sinp,
    const float* __restrict__ qw, const float* __restrict__ kw)
{
    int d = threadIdx.x;
    int hh = blockIdx.x;
    int s = blockIdx.y;
    int b = blockIdx.z;
    int kv = hh / 6;
    int slot = hh % 6;

    const float* row = g_qkv + ((size_t)(b * SS + s)) * QKVN + (size_t)hh * HD;
    float x = row[d];
    float out;

    __shared__ float red[HD];

    if (slot < 5) {
        // RoPE
        float c = cosp[(size_t)s * HD + d];
        float sn = sinp[(size_t)s * HD + d];
        float other = row[d < 64 ? d + 64 : d - 64];
        float rot = (d < 64) ? -other : other;
        out = x * c + rot * sn;
        // RMSNorm over head dim
        red[d] = out * out;
        __syncthreads();
#pragma unroll
        for (int off = 64; off > 0; off >>= 1) {
            if (d < off) red[d] += red[d + off];
            __syncthreads();
        }
        float inv = rsqrtf(red[0] / 128.0f + 1e-5f);
        const float* w = (slot < 4) ? qw : kw;
        out = w[d] * (out * inv);
    } else {
        out = x;  // v: plain copy
    }

    if (slot < 4) {
        int h = kv * 4 + slot;
        g_q[(((size_t)(b * NH + h)) * SS + s) * HD + d] = out;
    } else if (slot == 4) {
        g_k[(((size_t)(b * HKV + kv)) * SS + s) * HD + d] = out;
    } else {
        g_v[(((size_t)(b * HKV + kv)) * SS + s) * HD + d] = out;
    }
}

// ---------------- row softmax over S=2048, one block (256 threads) per row --------------
__global__ __launch_bounds__(256) void softmax_kernel()
{
    size_t rowIdx = blockIdx.x;
    float* x = g_scores + rowIdx * (size_t)SS;
    int t = threadIdx.x;

    float v[8];
    float m = -INFINITY;
#pragma unroll
    for (int i = 0; i < 8; i++) {
        v[i] = x[t + i * 256];
        m = fmaxf(m, v[i]);
    }

    __shared__ float red[256];
    red[t] = m;
    __syncthreads();
#pragma unroll
    for (int off = 128; off > 0; off >>= 1) {
        if (t < off) red[t] = fmaxf(red[t], red[t + off]);
        __syncthreads();
    }
    m = red[0];
    __syncthreads();

    float sum = 0.0f;
#pragma unroll
    for (int i = 0; i < 8; i++) {
        v[i] = expf(v[i] - m);
        sum += v[i];
    }
    red[t] = sum;
    __syncthreads();
#pragma unroll
    for (int off = 128; off > 0; off >>= 1) {
        if (t < off) red[t] += red[t + off];
        __syncthreads();
    }
    float inv = 1.0f / red[0];
#pragma unroll
    for (int i = 0; i < 8; i++)
        x[t + i * 256] = v[i] * inv;
}

// ---------------- launcher ----------------
extern "C" void kernel_launch(void* const* d_in, const int* in_sizes, int n_in,
                              void* d_out, int out_size)
{
    (void)in_sizes; (void)n_in; (void)out_size;
    const float* hidden = (const float*)d_in[0];  // [B,S,D]
    const float* cosp   = (const float*)d_in[1];  // [1,S,128]
    const float* sinp   = (const float*)d_in[2];  // [1,S,128]
    const float* w_qkv  = (const float*)d_in[3];  // [6144,4096]
    const float* w_o    = (const float*)d_in[4];  // [4096,4096]
    const float* qnw    = (const float*)d_in[5];  // [128]
    const float* knw    = (const float*)d_in[6];  // [128]
    float* out = (float*)d_out;                   // [B,S,D]

    float *p_qkv, *p_q, *p_k, *p_v, *p_sc, *p_at;
    cudaGetSymbolAddress((void**)&p_qkv, g_qkv);
    cudaGetSymbolAddress((void**)&p_q,   g_q);
    cudaGetSymbolAddress((void**)&p_k,   g_k);
    cudaGetSymbolAddress((void**)&p_v,   g_v);
    cudaGetSymbolAddress((void**)&p_sc,  g_scores);
    cudaGetSymbolAddress((void**)&p_at,  g_attn);

    const float scale = 0.08838834764831843f;  // 1/sqrt(128)

    // 1) qkv = hidden @ w_qkv^T   [4096, 6144]
    gemm_nt<<<dim3(QKVN / 128, (BB * SS) / 128, 1), 256>>>(
        hidden, w_qkv, p_qkv, DD, DD, DD, QKVN, 0, 0, 0, 1.0f, 0, 0);

    // 2) RoPE + RMSNorm + split into Q/K/V
    rope_norm_kernel<<<dim3(HKV * 6, SS, BB), 128>>>(cosp, sinp, qnw, knw);

    // 3) scores = scale * Q @ K^T, batched over z = b*32 + h (GQA K indexing)
    gemm_nt<<<dim3(SS / 128, SS / 128, BB * NH), 256>>>(
        p_q, p_k, p_sc, HD, HD, HD, SS,
        (long long)SS * HD, (long long)SS * HD, (long long)SS * SS,
        scale, 1, 0);

    // 4) softmax over each score row
    softmax_kernel<<<dim3(BB * NH * SS), 256>>>();

    // 5) attn = P @ V  -> written to [B,S,32,HD] layout
    gemm_nn<<<dim3(1, SS / 128, BB * NH), 256>>>(
        p_sc, p_v, p_at, SS, SS, HD, DD,
        (long long)SS * SS, (long long)SS * HD, 0,
        1.0f, 1, 1);

    // 6) out = attn @ w_o^T
    gemm_nt<<<dim3(DD / 128, (BB * SS) / 128, 1), 256>>>(
        p_at, w_o, out, DD, DD, DD, DD, 0, 0, 0, 1.0f, 0, 0);
}

// round 9
// speedup vs baseline: 1.3255x; 1.3255x over previous
#include <cuda_runtime.h>
#include <math.h>
#include <cstdint>

#define BB 2
#define SS 2048
#define DD 4096
#define QKVN 6144
#define HKV 8
#define NH 32
#define HD 128

// ---------------- scratch (static device globals; no runtime allocation) ----------------
__device__ float g_qkv[(size_t)BB * SS * QKVN];        // 100.7 MB
__device__ float g_q[(size_t)BB * NH * SS * HD];       // 67 MB
__device__ float g_k[(size_t)BB * HKV * SS * HD];      // 16.8 MB
__device__ float g_vt[(size_t)BB * HKV * HD * SS];     // 16.8 MB (transposed: [b,kv,d,s])
__device__ float g_scores[(size_t)BB * NH * SS * SS];  // 1.07 GB
__device__ float g_attn[(size_t)BB * SS * DD];         // 67 MB

// ================= helpers =================
__device__ __forceinline__ uint32_t smem_to_u32(const void* smem_ptr) {
    uint32_t addr;
    asm("{ .reg .u64 tmp; cvta.to.shared.u64 tmp, %1; cvt.u32.u64 %0, tmp; }"
        : "=r"(addr) : "l"(smem_ptr));
    return addr;
}

__device__ __forceinline__ void cp_async16(uint32_t saddr, const void* gptr) {
    asm volatile("cp.async.cg.shared.global [%0], [%1], 16;" :: "r"(saddr), "l"(gptr));
}
__device__ __forceinline__ void cp_commit() {
    asm volatile("cp.async.commit_group;" ::: "memory");
}
template <int N>
__device__ __forceinline__ void cp_wait() {
    asm volatile("cp.async.wait_group %0;" :: "n"(N) : "memory");
}

// round-to-nearest tf32 (hi part of the 3xtf32 split)
__device__ __forceinline__ uint32_t f2tf32(float f) {
    uint32_t r;
    asm("cvt.rna.tf32.f32 %0, %1;" : "=r"(r) : "f"(f));
    return r;
}

// m16n8k8 tf32 MMA
__device__ __forceinline__ void mma_tf32(float* d, const uint32_t* a, const uint32_t* b) {
    asm volatile(
        "mma.sync.aligned.m16n8k8.row.col.f32.tf32.tf32.f32 "
        "{%0,%1,%2,%3}, {%4,%5,%6,%7}, {%8,%9}, {%0,%1,%2,%3};"
        : "+f"(d[0]), "+f"(d[1]), "+f"(d[2]), "+f"(d[3])
        : "r"(a[0]), "r"(a[1]), "r"(a[2]), "r"(a[3]),
          "r"(b[0]), "r"(b[1]));
}

// Smem tile: 128 rows x 32 floats, padded row stride 36 floats (conflict-free frags)
#define RS 36
#define BUFF (128 * RS)                 // floats per buffer
// dynamic smem: A[2][BUFF], B[2][BUFF] = 4*128*36*4 = 73728 bytes
static constexpr uint32_t SM_TOTAL = 4u * BUFF * 4u;

// ================= 3xtf32 mma.sync GEMM: C = alpha * A * B^T =================
// A: [M,K] K-major (lda floats), B: [N,K] K-major (ldb floats). Tile 128x128, BK=32.
// 256 threads = 8 warps (2 M x 4 N), warp tile 64x32 (4x4 m16n8k8 frags).
// Each fragment split hi/lo in registers; acc += ah*bh + al*bh + ah*bl (fp32-grade).
// bgqa: B batch index = (z>>5)*HKV + (z&31)/4 (GQA);  cmode: C into [B,S,32,HD].
__global__ __launch_bounds__(256) void tc_gemm(
    const float* __restrict__ Ag, const float* __restrict__ Bg, float* __restrict__ Cg,
    int K, int lda, int ldb, int ldc,
    long long sA, long long sB, long long sC, float alpha, int bgqa, int cmode)
{
    extern __shared__ float smf[];
    float* As = smf;
    float* Bs = smf + 2 * BUFF;
    uint32_t asU = smem_to_u32(As);
    uint32_t bsU = smem_to_u32(Bs);

    int tid = threadIdx.x;
    int warp = tid >> 5;
    int lane = tid & 31;
    int warpM = warp & 1;      // 0..1 -> M offset warpM*64
    int warpN = warp >> 1;     // 0..3 -> N offset warpN*32
    int grp = lane >> 2;       // 0..7
    int thr = lane & 3;        // 0..3

    int z = blockIdx.z;
    const float* A = Ag + (long long)z * sA;
    const float* B = Bg + (bgqa ? (long long)((z >> 5) * HKV + ((z & 31) >> 2)) * sB
                                : (long long)z * sB);
    float* C = cmode ? (Cg + (long long)(z >> 5) * SS * DD + (long long)(z & 31) * HD)
                     : (Cg + (long long)z * sC);

    // per-thread gmem/smem assignment: 4 pieces of 16B for each of A and B per chunk
    const float* pA[4];
    const float* pB[4];
    uint32_t dstW[4];  // word offset within buffer
#pragma unroll
    for (int j = 0; j < 4; j++) {
        int p = tid + 256 * j;
        int row = p >> 3;          // 0..127
        int c16 = p & 7;           // float4 index within 32-float row
        dstW[j] = (uint32_t)(row * RS + c16 * 4);
        pA[j] = A + (long long)(blockIdx.y * 128 + row) * lda + c16 * 4;
        pB[j] = B + (long long)(blockIdx.x * 128 + row) * ldb + c16 * 4;
    }

    float acc[4][4][4];
#pragma unroll
    for (int mi = 0; mi < 4; mi++)
#pragma unroll
        for (int ni = 0; ni < 4; ni++)
#pragma unroll
            for (int r = 0; r < 4; r++) acc[mi][ni][r] = 0.0f;

    const int NC = K >> 5;

    // prologue: stage chunk 0 into buffer 0
#pragma unroll
    for (int j = 0; j < 4; j++) {
        cp_async16(asU + dstW[j] * 4, pA[j]);
        cp_async16(bsU + dstW[j] * 4, pB[j]);
    }
    cp_commit();

    for (int kc = 0; kc < NC; kc++) {
        int buf = kc & 1;
        if (kc + 1 < NC) {
            int nbuf = (kc + 1) & 1;
#pragma unroll
            for (int j = 0; j < 4; j++) {
                cp_async16(asU + (nbuf * BUFF + dstW[j]) * 4, pA[j] + (kc + 1) * 32);
                cp_async16(bsU + (nbuf * BUFF + dstW[j]) * 4, pB[j] + (kc + 1) * 32);
            }
            cp_commit();
            cp_wait<1>();
        } else {
            cp_wait<0>();
        }
        __syncthreads();

        const float* AsW = As + buf * BUFF + (warpM * 64 + grp) * RS + thr;
        const float* BsW = Bs + buf * BUFF + (warpN * 32 + grp) * RS + thr;

#pragma unroll
        for (int ks = 0; ks < 4; ks++) {
            uint32_t ah[4][4], al[4][4], bh[4][2], bl[4][2];
#pragma unroll
            for (int mi = 0; mi < 4; mi++) {
                float f0 = AsW[(mi * 16) * RS + ks * 8];
                float f1 = AsW[(mi * 16 + 8) * RS + ks * 8];
                float f2 = AsW[(mi * 16) * RS + ks * 8 + 4];
                float f3 = AsW[(mi * 16 + 8) * RS + ks * 8 + 4];
                ah[mi][0] = f2tf32(f0); al[mi][0] = __float_as_uint(f0 - __uint_as_float(ah[mi][0]));
                ah[mi][1] = f2tf32(f1); al[mi][1] = __float_as_uint(f1 - __uint_as_float(ah[mi][1]));
                ah[mi][2] = f2tf32(f2); al[mi][2] = __float_as_uint(f2 - __uint_as_float(ah[mi][2]));
                ah[mi][3] = f2tf32(f3); al[mi][3] = __float_as_uint(f3 - __uint_as_float(ah[mi][3]));
            }
#pragma unroll
            for (int ni = 0; ni < 4; ni++) {
                float f0 = BsW[(ni * 8) * RS + ks * 8];
                float f1 = BsW[(ni * 8) * RS + ks * 8 + 4];
                bh[ni][0] = f2tf32(f0); bl[ni][0] = __float_as_uint(f0 - __uint_as_float(bh[ni][0]));
                bh[ni][1] = f2tf32(f1); bl[ni][1] = __float_as_uint(f1 - __uint_as_float(bh[ni][1]));
            }
#pragma unroll
            for (int mi = 0; mi < 4; mi++)
#pragma unroll
                for (int ni = 0; ni < 4; ni++) {
                    mma_tf32(acc[mi][ni], ah[mi], bh[ni]);   // hi*hi
                    mma_tf32(acc[mi][ni], al[mi], bh[ni]);   // lo*hi
                    mma_tf32(acc[mi][ni], ah[mi], bl[ni]);   // hi*lo
                }
        }
        __syncthreads();   // protect buffer `buf` before it is re-staged next iter
    }

    // ---- epilogue ----
#pragma unroll
    for (int mi = 0; mi < 4; mi++) {
        int row0 = blockIdx.y * 128 + warpM * 64 + mi * 16 + grp;
#pragma unroll
        for (int ni = 0; ni < 4; ni++) {
            int col = blockIdx.x * 128 + warpN * 32 + ni * 8 + thr * 2;
            float2 v0 = make_float2(acc[mi][ni][0] * alpha, acc[mi][ni][1] * alpha);
            float2 v1 = make_float2(acc[mi][ni][2] * alpha, acc[mi][ni][3] * alpha);
            *(float2*)(C + (long long)row0 * ldc + col) = v0;
            *(float2*)(C + (long long)(row0 + 8) * ldc + col) = v1;
        }
    }
}

// ---------------- RoPE + RMSNorm + QKV split (V written transposed) ----------------
// grid: (48 head-slots, S, B), block: 128 (one thread per dim)
// slot layout in qkv row: hh = kv*6 + slot; slot 0..3 = q heads, 4 = k, 5 = v
__global__ __launch_bounds__(128) void rope_norm_kernel(
    const float* __restrict__ cosp, const float* __restrict__ sinp,
    const float* __restrict__ qw, const float* __restrict__ kw)
{
    int d = threadIdx.x;
    int hh = blockIdx.x;
    int s = blockIdx.y;
    int b = blockIdx.z;
    int kv = hh / 6;
    int slot = hh % 6;

    const float* row = g_qkv + ((size_t)(b * SS + s)) * QKVN + (size_t)hh * HD;
    float x = row[d];
    float out;

    __shared__ float red[HD];

    if (slot < 5) {
        float c = cosp[(size_t)s * HD + d];
        float sn = sinp[(size_t)s * HD + d];
        float other = row[d < 64 ? d + 64 : d - 64];
        float rot = (d < 64) ? -other : other;
        out = x * c + rot * sn;
        red[d] = out * out;
        __syncthreads();
#pragma unroll
        for (int off = 64; off > 0; off >>= 1) {
            if (d < off) red[d] += red[d + off];
            __syncthreads();
        }
        float inv = rsqrtf(red[0] / 128.0f + 1e-5f);
        const float* w = (slot < 4) ? qw : kw;
        out = w[d] * (out * inv);
    } else {
        out = x;  // v: plain copy
    }

    if (slot < 4) {
        int h = kv * 4 + slot;
        g_q[(((size_t)(b * NH + h)) * SS + s) * HD + d] = out;
    } else if (slot == 4) {
        g_k[(((size_t)(b * HKV + kv)) * SS + s) * HD + d] = out;
    } else {
        // transposed store: [b, kv, d, s] so PV can run as an nt-GEMM
        g_vt[(((size_t)(b * HKV + kv)) * HD + d) * SS + s] = out;
    }
}

// ---------------- row softmax over S=2048, one block (256 threads) per row --------------
__global__ __launch_bounds__(256) void softmax_kernel()
{
    size_t rowIdx = blockIdx.x;
    float* x = g_scores + rowIdx * (size_t)SS;
    int t = threadIdx.x;

    float v[8];
    float m = -INFINITY;
#pragma unroll
    for (int i = 0; i < 8; i++) {
        v[i] = x[t + i * 256];
        m = fmaxf(m, v[i]);
    }

    __shared__ float red[256];
    red[t] = m;
    __syncthreads();
#pragma unroll
    for (int off = 128; off > 0; off >>= 1) {
        if (t < off) red[t] = fmaxf(red[t], red[t + off]);
        __syncthreads();
    }
    m = red[0];
    __syncthreads();

    float sum = 0.0f;
#pragma unroll
    for (int i = 0; i < 8; i++) {
        v[i] = expf(v[i] - m);
        sum += v[i];
    }
    red[t] = sum;
    __syncthreads();
#pragma unroll
    for (int off = 128; off > 0; off >>= 1) {
        if (t < off) red[t] += red[t + off];
        __syncthreads();
    }
    float inv = 1.0f / red[0];
#pragma unroll
    for (int i = 0; i < 8; i++)
        x[t + i * 256] = v[i] * inv;
}

// ---------------- launcher ----------------
extern "C" void kernel_launch(void* const* d_in, const int* in_sizes, int n_in,
                              void* d_out, int out_size)
{
    (void)in_sizes; (void)n_in; (void)out_size;
    const float* hidden = (const float*)d_in[0];  // [B,S,D]
    const float* cosp   = (const float*)d_in[1];  // [1,S,128]
    const float* sinp   = (const float*)d_in[2];  // [1,S,128]
    const float* w_qkv  = (const float*)d_in[3];  // [6144,4096]
    const float* w_o    = (const float*)d_in[4];  // [4096,4096]
    const float* qnw    = (const float*)d_in[5];  // [128]
    const float* knw    = (const float*)d_in[6];  // [128]
    float* out = (float*)d_out;                   // [B,S,D]

    float *p_qkv, *p_q, *p_k, *p_vt, *p_sc, *p_at;
    cudaGetSymbolAddress((void**)&p_qkv, g_qkv);
    cudaGetSymbolAddress((void**)&p_q,   g_q);
    cudaGetSymbolAddress((void**)&p_k,   g_k);
    cudaGetSymbolAddress((void**)&p_vt,  g_vt);
    cudaGetSymbolAddress((void**)&p_sc,  g_scores);
    cudaGetSymbolAddress((void**)&p_at,  g_attn);

    cudaFuncSetAttribute(tc_gemm, cudaFuncAttributeMaxDynamicSharedMemorySize, SM_TOTAL);

    const float scale = 0.08838834764831843f;  // 1/sqrt(128)

    // 1) qkv = hidden @ w_qkv^T   [4096, 6144]
    tc_gemm<<<dim3(QKVN / 128, (BB * SS) / 128, 1), 256, SM_TOTAL>>>(
        hidden, w_qkv, p_qkv, DD, DD, DD, QKVN, 0, 0, 0, 1.0f, 0, 0);

    // 2) RoPE + RMSNorm + split (V transposed)
    rope_norm_kernel<<<dim3(HKV * 6, SS, BB), 128>>>(cosp, sinp, qnw, knw);

    // 3) scores = scale * Q @ K^T, batched over z = b*32 + h (GQA K indexing)
    tc_gemm<<<dim3(SS / 128, SS / 128, BB * NH), 256, SM_TOTAL>>>(
        p_q, p_k, p_sc, HD, HD, HD, SS,
        (long long)SS * HD, (long long)SS * HD, (long long)SS * SS,
        scale, 1, 0);

    // 4) softmax over each score row
    softmax_kernel<<<dim3(BB * NH * SS), 256>>>();

    // 5) attn = P @ Vt^T  -> written to [B,S,32,HD] layout
    tc_gemm<<<dim3(1, SS / 128, BB * NH), 256, SM_TOTAL>>>(
        p_sc, p_vt, p_at, SS, SS, SS, DD,
        (long long)SS * SS, (long long)HD * SS, 0,
        1.0f, 1, 1);

    // 6) out = attn @ w_o^T
    tc_gemm<<<dim3(DD / 128, (BB * SS) / 128, 1), 256, SM_TOTAL>>>(
        p_at, w_o, out, DD, DD, DD, DD, 0, 0, 0, 1.0f, 0, 0);
}

// round 11
// speedup vs baseline: 2.2028x; 1.6619x over previous
#include <cuda_runtime.h>
#include <cuda_bf16.h>
#include <math.h>
#include <cstdint>

#define BB 2
#define SS 2048
#define DD 4096
#define QKVN 6144
#define HKV 8
#define NH 32
#define HD 128

// ---------------- scratch (static device globals; no runtime allocation) ----------------
__device__ float g_qkv[(size_t)BB * SS * QKVN];            // fp32, feeds rope
__device__ float g_scores[(size_t)BB * NH * SS * SS];      // fp32, feeds softmax
// hi/lo bf16 operand arrays
__device__ __nv_bfloat16 g_hh[(size_t)BB * SS * DD];       // hidden hi
__device__ __nv_bfloat16 g_hl[(size_t)BB * SS * DD];       // hidden lo
__device__ __nv_bfloat16 g_wqh[(size_t)QKVN * DD];
__device__ __nv_bfloat16 g_wql[(size_t)QKVN * DD];
__device__ __nv_bfloat16 g_woh[(size_t)DD * DD];
__device__ __nv_bfloat16 g_wol[(size_t)DD * DD];
__device__ __nv_bfloat16 g_qh[(size_t)BB * NH * SS * HD];
__device__ __nv_bfloat16 g_ql[(size_t)BB * NH * SS * HD];
__device__ __nv_bfloat16 g_kh[(size_t)BB * HKV * SS * HD];
__device__ __nv_bfloat16 g_kl[(size_t)BB * HKV * SS * HD];
__device__ __nv_bfloat16 g_vth[(size_t)BB * HKV * HD * SS];   // V transposed [b,kv,d,s]
__device__ __nv_bfloat16 g_vtl[(size_t)BB * HKV * HD * SS];
__device__ __nv_bfloat16 g_ph[(size_t)BB * NH * SS * SS];     // softmax probs hi
__device__ __nv_bfloat16 g_pl[(size_t)BB * NH * SS * SS];     // softmax probs lo
__device__ __nv_bfloat16 g_ah[(size_t)BB * SS * DD];          // attn out hi [B,S,32,HD]
__device__ __nv_bfloat16 g_al[(size_t)BB * SS * DD];          // attn out lo

// ================= helpers =================
__device__ __forceinline__ uint32_t smem_to_u32(const void* smem_ptr) {
    uint32_t addr;
    asm("{ .reg .u64 tmp; cvta.to.shared.u64 tmp, %1; cvt.u32.u64 %0, tmp; }"
        : "=r"(addr) : "l"(smem_ptr));
    return addr;
}

__device__ __forceinline__ void cp_async16(uint32_t saddr, const void* gptr) {
    asm volatile("cp.async.cg.shared.global [%0], [%1], 16;" :: "r"(saddr), "l"(gptr));
}
__device__ __forceinline__ void cp_commit() {
    asm volatile("cp.async.commit_group;" ::: "memory");
}
template <int N>
__device__ __forceinline__ void cp_wait() {
    asm volatile("cp.async.wait_group %0;" :: "n"(N) : "memory");
}

// m16n8k16 bf16 MMA, fp32 accumulate
__device__ __forceinline__ void mma_bf16(float* d, const uint32_t* a, const uint32_t* b) {
    asm volatile(
        "mma.sync.aligned.m16n8k16.row.col.f32.bf16.bf16.f32 "
        "{%0,%1,%2,%3}, {%4,%5,%6,%7}, {%8,%9}, {%0,%1,%2,%3};"
        : "+f"(d[0]), "+f"(d[1]), "+f"(d[2]), "+f"(d[3])
        : "r"(a[0]), "r"(a[1]), "r"(a[2]), "r"(a[3]),
          "r"(b[0]), "r"(b[1]));
}

__device__ __forceinline__ void split_bf16(float v, __nv_bfloat16& h, __nv_bfloat16& l) {
    h = __float2bfloat16(v);
    l = __float2bfloat16(v - __bfloat162float(h));
}

// Smem tile geometry: 128 rows x 32 bf16, row stride 20 words (40 halves, 80B).
// grp*20 + thr covers all 32 banks -> conflict-free fragment loads and STS.128.
#define RSW 20
#define TILEW (128 * RSW)               // 2560 words per tile
#define BUFW  (4 * TILEW)               // Ah,Al,Bh,Bl per buffer = 10240 words
static constexpr uint32_t SM_TOTAL = 2u * BUFW * 4u;   // 81920 bytes

// ================= bf16x3 mma.sync GEMM: C = alpha * A * B^T =================
// A: [M,K] K-major hi/lo (lda halves), B: [N,K] K-major hi/lo (ldb halves).
// Tile 128x128, BK=32, 256 threads = 8 warps (2M x 4N), warp tile 64x32.
// acc += Ah*Bh + Al*Bh + Ah*Bl  (Ootomo 3-term; fp32-grade).
// bgqa: B batch = (z>>5)*HKV + (z&31)/4.  outmode 0: fp32 C (+z*sC);
// outmode 1: bf16 hi/lo C at [B,S,32,HD] (Ch/Cl).
__global__ __launch_bounds__(256, 2) void tc_gemm(
    const __nv_bfloat16* __restrict__ Ah, const __nv_bfloat16* __restrict__ Al,
    const __nv_bfloat16* __restrict__ Bh, const __nv_bfloat16* __restrict__ Bl,
    float* __restrict__ Cf, __nv_bfloat16* __restrict__ Ch, __nv_bfloat16* __restrict__ Cl,
    int K, int lda, int ldb, int ldc,
    long long sA, long long sB, long long sC, float alpha, int bgqa, int outmode)
{
    extern __shared__ uint32_t smw[];
    uint32_t asU = smem_to_u32(smw);

    int tid = threadIdx.x;
    int warp = tid >> 5;
    int lane = tid & 31;
    int warpM = warp & 1;
    int warpN = warp >> 1;
    int grp = lane >> 2;       // 0..7
    int thr = lane & 3;        // 0..3

    int z = blockIdx.z;
    long long aOff = (long long)z * sA;
    long long bOff = (bgqa ? (long long)((z >> 5) * HKV + ((z & 31) >> 2)) * sB
                           : (long long)z * sB);

    // ---- staging assignment: 4 tiles x 2 pieces (16B) per thread per chunk ----
    const __nv_bfloat16* gsrc[4][2];
    uint32_t sdst[4][2];
#pragma unroll
    for (int j = 0; j < 2; j++) {
        int p = tid + 256 * j;
        int row = p >> 2;          // 0..127
        int c16 = p & 3;           // 16B piece within 64B row
        uint32_t w = (uint32_t)(row * RSW + c16 * 4);
        long long ga = aOff + (long long)(blockIdx.y * 128 + row) * lda + c16 * 8;
        long long gb = bOff + (long long)(blockIdx.x * 128 + row) * ldb + c16 * 8;
        gsrc[0][j] = Ah + ga;  sdst[0][j] = asU + (0 * TILEW + w) * 4;
        gsrc[1][j] = Al + ga;  sdst[1][j] = asU + (1 * TILEW + w) * 4;
        gsrc[2][j] = Bh + gb;  sdst[2][j] = asU + (2 * TILEW + w) * 4;
        gsrc[3][j] = Bl + gb;  sdst[3][j] = asU + (3 * TILEW + w) * 4;
    }

    float acc[4][4][4];
#pragma unroll
    for (int mi = 0; mi < 4; mi++)
#pragma unroll
        for (int ni = 0; ni < 4; ni++)
#pragma unroll
            for (int r = 0; r < 4; r++) acc[mi][ni][r] = 0.0f;

    const int NC = K >> 5;

    // prologue: chunk 0 -> buffer 0
#pragma unroll
    for (int t = 0; t < 4; t++)
#pragma unroll
        for (int j = 0; j < 2; j++)
            cp_async16(sdst[t][j], gsrc[t][j]);
    cp_commit();

    for (int kc = 0; kc < NC; kc++) {
        int buf = kc & 1;
        if (kc + 1 < NC) {
            uint32_t nb = ((kc + 1) & 1) * BUFW * 4;   // byte offset of next buffer
#pragma unroll
            for (int t = 0; t < 4; t++)
#pragma unroll
                for (int j = 0; j < 2; j++)
                    cp_async16(sdst[t][j] + nb, gsrc[t][j] + (kc + 1) * 32);
            cp_commit();
            cp_wait<1>();
        } else {
            cp_wait<0>();
        }
        __syncthreads();

        const uint32_t* sA_h = smw + buf * BUFW + (warpM * 64 + grp) * RSW + thr;
        const uint32_t* sA_l = sA_h + TILEW;
        const uint32_t* sB_h = smw + buf * BUFW + 2 * TILEW + (warpN * 32 + grp) * RSW + thr;
        const uint32_t* sB_l = sB_h + TILEW;

#pragma unroll
        for (int ks = 0; ks < 2; ks++) {
            uint32_t bh[4][2], bl[4][2];
#pragma unroll
            for (int ni = 0; ni < 4; ni++) {
                bh[ni][0] = sB_h[(ni * 8) * RSW + ks * 8];
                bh[ni][1] = sB_h[(ni * 8) * RSW + ks * 8 + 4];
                bl[ni][0] = sB_l[(ni * 8) * RSW + ks * 8];
                bl[ni][1] = sB_l[(ni * 8) * RSW + ks * 8 + 4];
            }
#pragma unroll
            for (int mi = 0; mi < 4; mi++) {
                uint32_t ah[4], al[4];
                ah[0] = sA_h[(mi * 16) * RSW + ks * 8];
                ah[1] = sA_h[(mi * 16 + 8) * RSW + ks * 8];
                ah[2] = sA_h[(mi * 16) * RSW + ks * 8 + 4];
                ah[3] = sA_h[(mi * 16 + 8) * RSW + ks * 8 + 4];
                al[0] = sA_l[(mi * 16) * RSW + ks * 8];
                al[1] = sA_l[(mi * 16 + 8) * RSW + ks * 8];
                al[2] = sA_l[(mi * 16) * RSW + ks * 8 + 4];
                al[3] = sA_l[(mi * 16 + 8) * RSW + ks * 8 + 4];
#pragma unroll
                for (int ni = 0; ni < 4; ni++) {
                    mma_bf16(acc[mi][ni], ah, bh[ni]);   // hi*hi
                    mma_bf16(acc[mi][ni], al, bh[ni]);   // lo*hi
                    mma_bf16(acc[mi][ni], ah, bl[ni]);   // hi*lo
                }
            }
        }
        __syncthreads();
    }

    // ---- epilogue ----
    if (outmode == 0) {
        float* C = Cf + (long long)z * sC;
#pragma unroll
        for (int mi = 0; mi < 4; mi++) {
            int row0 = blockIdx.y * 128 + warpM * 64 + mi * 16 + grp;
#pragma unroll
            for (int ni = 0; ni < 4; ni++) {
                int col = blockIdx.x * 128 + warpN * 32 + ni * 8 + thr * 2;
                float2 v0 = make_float2(acc[mi][ni][0] * alpha, acc[mi][ni][1] * alpha);
                float2 v1 = make_float2(acc[mi][ni][2] * alpha, acc[mi][ni][3] * alpha);
                *(float2*)(C + (long long)row0 * ldc + col) = v0;
                *(float2*)(C + (long long)(row0 + 8) * ldc + col) = v1;
            }
        }
    } else {
        // bf16 hi/lo output into [B,S,32,HD]: b = z>>5, h = z&31
        long long base = (long long)(z >> 5) * SS * DD + (long long)(z & 31) * HD;
#pragma unroll
        for (int mi = 0; mi < 4; mi++) {
            int row0 = blockIdx.y * 128 + warpM * 64 + mi * 16 + grp;
#pragma unroll
            for (int ni = 0; ni < 4; ni++) {
                int col = blockIdx.x * 128 + warpN * 32 + ni * 8 + thr * 2;
#pragma unroll
                for (int half = 0; half < 2; half++) {
                    long long idx = base + (long long)(row0 + half * 8) * DD + col;
                    float v0 = acc[mi][ni][half * 2 + 0] * alpha;
                    float v1 = acc[mi][ni][half * 2 + 1] * alpha;
                    __nv_bfloat16 h0, l0, h1, l1;
                    split_bf16(v0, h0, l0);
                    split_bf16(v1, h1, l1);
                    __nv_bfloat162 hh; hh.x = h0; hh.y = h1;
                    __nv_bfloat162 ll; ll.x = l0; ll.y = l1;
                    *(__nv_bfloat162*)(Ch + idx) = hh;
                    *(__nv_bfloat162*)(Cl + idx) = ll;
                }
            }
        }
    }
}

// ---------------- fp32 -> bf16 hi/lo split (grid-stride over float4) ----------------
__global__ __launch_bounds__(256) void split_kernel(
    const float* __restrict__ src, __nv_bfloat16* __restrict__ hi,
    __nv_bfloat16* __restrict__ lo, long long n4)
{
    long long i = (long long)blockIdx.x * 256 + threadIdx.x;
    if (i >= n4) return;
    float4 v = *(const float4*)(src + i * 4);
    __nv_bfloat16 h0, l0, h1, l1, h2, l2, h3, l3;
    split_bf16(v.x, h0, l0);
    split_bf16(v.y, h1, l1);
    split_bf16(v.z, h2, l2);
    split_bf16(v.w, h3, l3);
    __nv_bfloat162* hp = (__nv_bfloat162*)(hi + i * 4);
    __nv_bfloat162* lp = (__nv_bfloat162*)(lo + i * 4);
    __nv_bfloat162 a; a.x = h0; a.y = h1;
    __nv_bfloat162 b; b.x = h2; b.y = h3;
    __nv_bfloat162 c; c.x = l0; c.y = l1;
    __nv_bfloat162 d; d.x = l2; d.y = l3;
    hp[0] = a; hp[1] = b;
    lp[0] = c; lp[1] = d;
}

// ---------------- RoPE + RMSNorm + QKV split (writes hi/lo bf16) ----------------
// grid: (48 head-slots, S, B), block: 128. hh = kv*6 + slot; slot 0..3=q, 4=k, 5=v
__global__ __launch_bounds__(128) void rope_norm_kernel(
    const float* __restrict__ cosp, const float* __restrict__ sinp,
    const float* __restrict__ qw, const float* __restrict__ kw)
{
    int d = threadIdx.x;
    int hh = blockIdx.x;
    int s = blockIdx.y;
    int b = blockIdx.z;
    int kv = hh / 6;
    int slot = hh % 6;

    const float* row = g_qkv + ((size_t)(b * SS + s)) * QKVN + (size_t)hh * HD;
    float x = row[d];
    float out;

    __shared__ float red[HD];

    if (slot < 5) {
        float c = cosp[(size_t)s * HD + d];
        float sn = sinp[(size_t)s * HD + d];
        float other = row[d < 64 ? d + 64 : d - 64];
        float rot = (d < 64) ? -other : other;
        out = x * c + rot * sn;
        red[d] = out * out;
        __syncthreads();
#pragma unroll
        for (int off = 64; off > 0; off >>= 1) {
            if (d < off) red[d] += red[d + off];
            __syncthreads();
        }
        float inv = rsqrtf(red[0] / 128.0f + 1e-5f);
        const float* w = (slot < 4) ? qw : kw;
        out = w[d] * (out * inv);
    } else {
        out = x;  // v: plain copy
    }

    __nv_bfloat16 h, l;
    split_bf16(out, h, l);

    if (slot < 4) {
        int hq = kv * 4 + slot;
        size_t idx = (((size_t)(b * NH + hq)) * SS + s) * HD + d;
        g_qh[idx] = h; g_ql[idx] = l;
    } else if (slot == 4) {
        size_t idx = (((size_t)(b * HKV + kv)) * SS + s) * HD + d;
        g_kh[idx] = h; g_kl[idx] = l;
    } else {
        size_t idx = (((size_t)(b * HKV + kv)) * HD + d) * SS + s;   // transposed
        g_vth[idx] = h; g_vtl[idx] = l;
    }
}

// ---------------- row softmax over S=2048 -> bf16 hi/lo probs ----------------
__global__ __launch_bounds__(256) void softmax_kernel()
{
    size_t rowIdx = blockIdx.x;
    const float* x = g_scores + rowIdx * (size_t)SS;
    __nv_bfloat16* ph = g_ph + rowIdx * (size_t)SS;
    __nv_bfloat16* pl = g_pl + rowIdx * (size_t)SS;
    int t = threadIdx.x;

    float v[8];
    float m = -INFINITY;
#pragma unroll
    for (int i = 0; i < 8; i++) {
        v[i] = x[t + i * 256];
        m = fmaxf(m, v[i]);
    }

    __shared__ float red[256];
    red[t] = m;
    __syncthreads();
#pragma unroll
    for (int off = 128; off > 0; off >>= 1) {
        if (t < off) red[t] = fmaxf(red[t], red[t + off]);
        __syncthreads();
    }
    m = red[0];
    __syncthreads();

    float sum = 0.0f;
#pragma unroll
    for (int i = 0; i < 8; i++) {
        v[i] = expf(v[i] - m);
        sum += v[i];
    }
    red[t] = sum;
    __syncthreads();
#pragma unroll
    for (int off = 128; off > 0; off >>= 1) {
        if (t < off) red[t] += red[t + off];
        __syncthreads();
    }
    float inv = 1.0f / red[0];
#pragma unroll
    for (int i = 0; i < 8; i++) {
        float p = v[i] * inv;
        __nv_bfloat16 h, l;
        split_bf16(p, h, l);
        ph[t + i * 256] = h;
        pl[t + i * 256] = l;
    }
}

// ---------------- launcher ----------------
extern "C" void kernel_launch(void* const* d_in, const int* in_sizes, int n_in,
                              void* d_out, int out_size)
{
    (void)in_sizes; (void)n_in; (void)out_size;
    const float* hidden = (const float*)d_in[0];  // [B,S,D]
    const float* cosp   = (const float*)d_in[1];  // [1,S,128]
    const float* sinp   = (const float*)d_in[2];  // [1,S,128]
    const float* w_qkv  = (const float*)d_in[3];  // [6144,4096]
    const float* w_o    = (const float*)d_in[4];  // [4096,4096]
    const float* qnw    = (const float*)d_in[5];  // [128]
    const float* knw    = (const float*)d_in[6];  // [128]
    float* out = (float*)d_out;                   // [B,S,D]

    float *p_qkv, *p_sc;
    __nv_bfloat16 *p_hh, *p_hl, *p_wqh, *p_wql, *p_woh, *p_wol;
    __nv_bfloat16 *p_qhh, *p_qll, *p_kh, *p_kl, *p_vth, *p_vtl, *p_ph, *p_pl, *p_ah, *p_al;
    cudaGetSymbolAddress((void**)&p_qkv, g_qkv);
    cudaGetSymbolAddress((void**)&p_sc,  g_scores);
    cudaGetSymbolAddress((void**)&p_hh,  g_hh);
    cudaGetSymbolAddress((void**)&p_hl,  g_hl);
    cudaGetSymbolAddress((void**)&p_wqh, g_wqh);
    cudaGetSymbolAddress((void**)&p_wql, g_wql);
    cudaGetSymbolAddress((void**)&p_woh, g_woh);
    cudaGetSymbolAddress((void**)&p_wol, g_wol);
    cudaGetSymbolAddress((void**)&p_qhh, g_qh);
    cudaGetSymbolAddress((void**)&p_qll, g_ql);
    cudaGetSymbolAddress((void**)&p_kh,  g_kh);
    cudaGetSymbolAddress((void**)&p_kl,  g_kl);
    cudaGetSymbolAddress((void**)&p_vth, g_vth);
    cudaGetSymbolAddress((void**)&p_vtl, g_vtl);
    cudaGetSymbolAddress((void**)&p_ph,  g_ph);
    cudaGetSymbolAddress((void**)&p_pl,  g_pl);
    cudaGetSymbolAddress((void**)&p_ah,  g_ah);
    cudaGetSymbolAddress((void**)&p_al,  g_al);

    cudaFuncSetAttribute(tc_gemm, cudaFuncAttributeMaxDynamicSharedMemorySize, SM_TOTAL);

    const float scale = 0.08838834764831843f;  // 1/sqrt(128)

    // 0) split fp32 inputs into bf16 hi/lo
    long long nh4 = (long long)BB * SS * DD / 4;
    long long nq4 = (long long)QKVN * DD / 4;
    long long no4 = (long long)DD * DD / 4;
    split_kernel<<<(unsigned)((nh4 + 255) / 256), 256>>>(hidden, p_hh, p_hl, nh4);
    split_kernel<<<(unsigned)((nq4 + 255) / 256), 256>>>(w_qkv, p_wqh, p_wql, nq4);
    split_kernel<<<(unsigned)((no4 + 255) / 256), 256>>>(w_o, p_woh, p_wol, no4);

    // 1) qkv = hidden @ w_qkv^T   [4096, 6144] fp32
    tc_gemm<<<dim3(QKVN / 128, (BB * SS) / 128, 1), 256, SM_TOTAL>>>(
        p_hh, p_hl, p_wqh, p_wql, p_qkv, nullptr, nullptr,
        DD, DD, DD, QKVN, 0, 0, 0, 1.0f, 0, 0);

    // 2) RoPE + RMSNorm + split (q/k/vt hi+lo)
    rope_norm_kernel<<<dim3(HKV * 6, SS, BB), 128>>>(cosp, sinp, qnw, knw);

    // 3) scores = scale * Q @ K^T (fp32), batched z = b*32+h, GQA K
    tc_gemm<<<dim3(SS / 128, SS / 128, BB * NH), 256, SM_TOTAL>>>(
        p_qhh, p_qll, p_kh, p_kl, p_sc, nullptr, nullptr,
        HD, HD, HD, SS,
        (long long)SS * HD, (long long)SS * HD, (long long)SS * SS,
        scale, 1, 0);

    // 4) softmax -> P hi/lo bf16
    softmax_kernel<<<dim3(BB * NH * SS), 256>>>();

    // 5) attn = P @ Vt^T -> bf16 hi/lo at [B,S,32,HD]
    tc_gemm<<<dim3(1, SS / 128, BB * NH), 256, SM_TOTAL>>>(
        p_ph, p_pl, p_vth, p_vtl, nullptr, p_ah, p_al,
        SS, SS, SS, DD,
        (long long)SS * SS, (long long)HD * SS, 0,
        1.0f, 1, 1);

    // 6) out = attn @ w_o^T (fp32)
    tc_gemm<<<dim3(DD / 128, (BB * SS) / 128, 1), 256, SM_TOTAL>>>(
        p_ah, p_al, p_woh, p_wol, out, nullptr, nullptr,
        DD, DD, DD, DD, 0, 0, 0, 1.0f, 0, 0);
}

// round 12
// speedup vs baseline: 2.8841x; 1.3093x over previous
#include <cuda_runtime.h>
#include <cuda_bf16.h>
#include <math.h>
#include <cstdint>

#define BB 2
#define SS 2048
#define DD 4096
#define QKVN 6144
#define HKV 8
#define NH 32
#define HD 128

// ---------------- scratch (static device globals; no runtime allocation) ----------------
__device__ float g_qkv[(size_t)BB * SS * QKVN];            // fp32, feeds rope
__device__ float g_scores[(size_t)BB * NH * SS * SS];      // fp32, feeds softmax
// hi/lo bf16 operand arrays
__device__ __nv_bfloat16 g_hh[(size_t)BB * SS * DD];       // hidden hi
__device__ __nv_bfloat16 g_hl[(size_t)BB * SS * DD];       // hidden lo
__device__ __nv_bfloat16 g_wqh[(size_t)QKVN * DD];
__device__ __nv_bfloat16 g_wql[(size_t)QKVN * DD];
__device__ __nv_bfloat16 g_woh[(size_t)DD * DD];
__device__ __nv_bfloat16 g_wol[(size_t)DD * DD];
__device__ __nv_bfloat16 g_qh[(size_t)BB * NH * SS * HD];
__device__ __nv_bfloat16 g_ql[(size_t)BB * NH * SS * HD];
__device__ __nv_bfloat16 g_kh[(size_t)BB * HKV * SS * HD];
__device__ __nv_bfloat16 g_kl[(size_t)BB * HKV * SS * HD];
__device__ __nv_bfloat16 g_vth[(size_t)BB * HKV * HD * SS];   // V transposed [b,kv,d,s]
__device__ __nv_bfloat16 g_vtl[(size_t)BB * HKV * HD * SS];
__device__ __nv_bfloat16 g_ph[(size_t)BB * NH * SS * SS];     // softmax probs hi
__device__ __nv_bfloat16 g_pl[(size_t)BB * NH * SS * SS];     // softmax probs lo
__device__ __nv_bfloat16 g_ah[(size_t)BB * SS * DD];          // attn out hi [B,S,32,HD]
__device__ __nv_bfloat16 g_al[(size_t)BB * SS * DD];          // attn out lo

// ================= helpers =================
__device__ __forceinline__ uint32_t smem_to_u32(const void* smem_ptr) {
    uint32_t addr;
    asm("{ .reg .u64 tmp; cvta.to.shared.u64 tmp, %1; cvt.u32.u64 %0, tmp; }"
        : "=r"(addr) : "l"(smem_ptr));
    return addr;
}

__device__ __forceinline__ void cp_async16(uint32_t saddr, const void* gptr) {
    asm volatile("cp.async.cg.shared.global [%0], [%1], 16;" :: "r"(saddr), "l"(gptr));
}
__device__ __forceinline__ void cp_commit() {
    asm volatile("cp.async.commit_group;" ::: "memory");
}
template <int N>
__device__ __forceinline__ void cp_wait() {
    asm volatile("cp.async.wait_group %0;" :: "n"(N) : "memory");
}

// ldmatrix x4: four 8x8 b16 matrices, lane L supplies one 16B row address
__device__ __forceinline__ void ldsm4(uint32_t* r, uint32_t addr) {
    asm volatile("ldmatrix.sync.aligned.m8n8.x4.shared.b16 {%0,%1,%2,%3}, [%4];"
        : "=r"(r[0]), "=r"(r[1]), "=r"(r[2]), "=r"(r[3]) : "r"(addr));
}

// m16n8k16 bf16 MMA, fp32 accumulate
__device__ __forceinline__ void mma_bf16(float* d, const uint32_t* a, const uint32_t* b) {
    asm volatile(
        "mma.sync.aligned.m16n8k16.row.col.f32.bf16.bf16.f32 "
        "{%0,%1,%2,%3}, {%4,%5,%6,%7}, {%8,%9}, {%0,%1,%2,%3};"
        : "+f"(d[0]), "+f"(d[1]), "+f"(d[2]), "+f"(d[3])
        : "r"(a[0]), "r"(a[1]), "r"(a[2]), "r"(a[3]),
          "r"(b[0]), "r"(b[1]));
}

__device__ __forceinline__ void split_bf16(float v, __nv_bfloat16& h, __nv_bfloat16& l) {
    h = __float2bfloat16(v);
    l = __float2bfloat16(v - __bfloat162float(h));
}

// Smem geometry: per stage 4 tiles (Ah, Al, Bh, Bl), each 128 rows x 32 bf16 = 64B rows,
// XOR swizzle: chunk16 ^= (row>>1)&3  -> conflict-free cp.async STS and ldmatrix reads.
#define TILE_B  8192u
#define STAGE_B 32768u
#define NSTAGE  3
static constexpr uint32_t SM_TOTAL = NSTAGE * STAGE_B;   // 98304 bytes

// ================= bf16x3 mma.sync GEMM: C = alpha * A * B^T =================
// A: [M,K] K-major hi/lo (lda halves), B: [N,K] K-major hi/lo (ldb halves).
// Tile 128x128, BK=32, 256 threads = 8 warps (2M x 4N), warp tile 64x32.
// acc += Ah*Bh + Al*Bh + Ah*Bl  (Ootomo 3-term; fp32-grade).
// 3-stage cp.async pipeline, ldmatrix fragment loads.
// bgqa: B batch = (z>>5)*HKV + (z&31)/4.  outmode 0: fp32 C (+z*sC);
// outmode 1: bf16 hi/lo C at [B,S,32,HD] (Ch/Cl).
__global__ __launch_bounds__(256, 2) void tc_gemm(
    const __nv_bfloat16* __restrict__ Ah, const __nv_bfloat16* __restrict__ Al,
    const __nv_bfloat16* __restrict__ Bh, const __nv_bfloat16* __restrict__ Bl,
    float* __restrict__ Cf, __nv_bfloat16* __restrict__ Ch, __nv_bfloat16* __restrict__ Cl,
    int K, int lda, int ldb, int ldc,
    long long sA, long long sB, long long sC, float alpha, int bgqa, int outmode)
{
    extern __shared__ uint32_t smw[];
    uint32_t asU = smem_to_u32(smw);

    int tid = threadIdx.x;
    int warp = tid >> 5;
    int lane = tid & 31;
    int warpM = warp & 1;
    int warpN = warp >> 1;
    int grp = lane >> 2;       // 0..7
    int thr = lane & 3;        // 0..3

    int z = blockIdx.z;
    long long aOff = (long long)z * sA;
    long long bOff = (bgqa ? (long long)((z >> 5) * HKV + ((z & 31) >> 2)) * sB
                           : (long long)z * sB);

    // ---- staging: thread covers (row0, c16) and (row0+64, c16); 16B pieces ----
    int row0 = tid >> 2;               // 0..63
    int c16 = tid & 3;
    uint32_t sdst0 = (uint32_t)(row0 * 64 + ((c16 ^ ((row0 >> 1) & 3)) * 16));
    const __nv_bfloat16* pAh = Ah + aOff + (long long)(blockIdx.y * 128 + row0) * lda + c16 * 8;
    const __nv_bfloat16* pAl = Al + aOff + (long long)(blockIdx.y * 128 + row0) * lda + c16 * 8;
    const __nv_bfloat16* pBh = Bh + bOff + (long long)(blockIdx.x * 128 + row0) * ldb + c16 * 8;
    const __nv_bfloat16* pBl = Bl + bOff + (long long)(blockIdx.x * 128 + row0) * ldb + c16 * 8;
    long long aStep = 64LL * lda;      // halves, j=1 piece (+64 rows)
    long long bStep = 64LL * ldb;

    // ---- ldmatrix per-lane address offsets (within a tile) ----
    // A (x4): lanes 0-7 rows m0-7 ch0 | 8-15 rows m8-15 ch0 | 16-23 rows m0-7 ch1 | 24-31 m8-15 ch1
    uint32_t aRowL = (uint32_t)(warpM * 64 + (lane & 15));
    uint32_t aOffL = aRowL * 64 + (((lane >> 4) ^ (((lane & 15) >> 1) & 3)) * 16);
    // B (x4): lanes 0-7 n0-7 ch0 | 8-15 n0-7 ch1 | 16-23 n8-15 ch0 | 24-31 n8-15 ch1
    uint32_t bRowL = (uint32_t)(warpN * 32 + ((lane >> 4) << 3) + (lane & 7));
    uint32_t bOffL = bRowL * 64 + (((((lane >> 3) & 1)) ^ (((lane & 7) >> 1) & 3)) * 16);

    float acc[4][4][4];
#pragma unroll
    for (int mi = 0; mi < 4; mi++)
#pragma unroll
        for (int ni = 0; ni < 4; ni++)
#pragma unroll
            for (int r = 0; r < 4; r++) acc[mi][ni][r] = 0.0f;

    const int NC = K >> 5;

    // ---- prologue: stage chunks 0 and 1 ----
#pragma unroll
    for (int s = 0; s < 2; s++) {
        uint32_t sb = asU + s * STAGE_B;
        int koff = s * 32;
        cp_async16(sb + sdst0,                 pAh + koff);
        cp_async16(sb + sdst0 + 4096,          pAh + aStep + koff);
        cp_async16(sb + 8192 + sdst0,          pAl + koff);
        cp_async16(sb + 8192 + sdst0 + 4096,   pAl + aStep + koff);
        cp_async16(sb + 16384 + sdst0,         pBh + koff);
        cp_async16(sb + 16384 + sdst0 + 4096,  pBh + bStep + koff);
        cp_async16(sb + 24576 + sdst0,         pBl + koff);
        cp_async16(sb + 24576 + sdst0 + 4096,  pBl + bStep + koff);
        cp_commit();
    }

    int stage = 0;       // stage of chunk kc
    int wstage = 2;      // stage to write (kc+2)
    for (int kc = 0; kc < NC; kc++) {
        cp_wait<1>();          // own group kc complete
        __syncthreads();       // stage-kc data visible; everyone done with kc-1

        if (kc + 2 < NC) {
            uint32_t sb = asU + wstage * STAGE_B;
            int koff = (kc + 2) * 32;
            cp_async16(sb + sdst0,                 pAh + koff);
            cp_async16(sb + sdst0 + 4096,          pAh + aStep + koff);
            cp_async16(sb + 8192 + sdst0,          pAl + koff);
            cp_async16(sb + 8192 + sdst0 + 4096,   pAl + aStep + koff);
            cp_async16(sb + 16384 + sdst0,         pBh + koff);
            cp_async16(sb + 16384 + sdst0 + 4096,  pBh + bStep + koff);
            cp_async16(sb + 24576 + sdst0,         pBl + koff);
            cp_async16(sb + 24576 + sdst0 + 4096,  pBl + bStep + koff);
        }
        cp_commit();           // always (empty group ok) to keep wait counting uniform

        uint32_t stb = asU + stage * STAGE_B;
        uint32_t aB = stb + aOffL;
        uint32_t bB = stb + 16384 + bOffL;

#pragma unroll
        for (int ks = 0; ks < 2; ks++) {
            uint32_t ax = ks ? (aB ^ 32) : aB;
            uint32_t bx = ks ? (bB ^ 32) : bB;
            uint32_t bhf[8], blf[8];
            ldsm4(bhf,     bx);               // ni 0,1 hi
            ldsm4(bhf + 4, bx + 1024);        // ni 2,3 hi
            ldsm4(blf,     bx + 8192);        // ni 0,1 lo
            ldsm4(blf + 4, bx + 8192 + 1024); // ni 2,3 lo
#pragma unroll
            for (int mi = 0; mi < 4; mi++) {
                uint32_t ahf[4], alf[4];
                ldsm4(ahf, ax + mi * 1024);
                ldsm4(alf, ax + 8192 + mi * 1024);
#pragma unroll
                for (int ni = 0; ni < 4; ni++)
                    mma_bf16(acc[mi][ni], ahf, bhf + ni * 2);   // hi*hi
#pragma unroll
                for (int ni = 0; ni < 4; ni++)
                    mma_bf16(acc[mi][ni], alf, bhf + ni * 2);   // lo*hi
#pragma unroll
                for (int ni = 0; ni < 4; ni++)
                    mma_bf16(acc[mi][ni], ahf, blf + ni * 2);   // hi*lo
            }
        }
        stage = (stage == NSTAGE - 1) ? 0 : stage + 1;
        wstage = (wstage == NSTAGE - 1) ? 0 : wstage + 1;
    }

    // ---- epilogue ----
    if (outmode == 0) {
        float* C = Cf + (long long)z * sC;
#pragma unroll
        for (int mi = 0; mi < 4; mi++) {
            int row = blockIdx.y * 128 + warpM * 64 + mi * 16 + grp;
#pragma unroll
            for (int ni = 0; ni < 4; ni++) {
                int col = blockIdx.x * 128 + warpN * 32 + ni * 8 + thr * 2;
                float2 v0 = make_float2(acc[mi][ni][0] * alpha, acc[mi][ni][1] * alpha);
                float2 v1 = make_float2(acc[mi][ni][2] * alpha, acc[mi][ni][3] * alpha);
                *(float2*)(C + (long long)row * ldc + col) = v0;
                *(float2*)(C + (long long)(row + 8) * ldc + col) = v1;
            }
        }
    } else {
        // bf16 hi/lo output into [B,S,32,HD]: b = z>>5, h = z&31
        long long base = (long long)(z >> 5) * SS * DD + (long long)(z & 31) * HD;
#pragma unroll
        for (int mi = 0; mi < 4; mi++) {
            int row = blockIdx.y * 128 + warpM * 64 + mi * 16 + grp;
#pragma unroll
            for (int ni = 0; ni < 4; ni++) {
                int col = blockIdx.x * 128 + warpN * 32 + ni * 8 + thr * 2;
#pragma unroll
                for (int half = 0; half < 2; half++) {
                    long long idx = base + (long long)(row + half * 8) * DD + col;
                    float v0 = acc[mi][ni][half * 2 + 0] * alpha;
                    float v1 = acc[mi][ni][half * 2 + 1] * alpha;
                    __nv_bfloat16 h0, l0, h1, l1;
                    split_bf16(v0, h0, l0);
                    split_bf16(v1, h1, l1);
                    __nv_bfloat162 hh; hh.x = h0; hh.y = h1;
                    __nv_bfloat162 ll; ll.x = l0; ll.y = l1;
                    *(__nv_bfloat162*)(Ch + idx) = hh;
                    *(__nv_bfloat162*)(Cl + idx) = ll;
                }
            }
        }
    }
}

// ---------------- fp32 -> bf16 hi/lo split (over float4) ----------------
__global__ __launch_bounds__(256) void split_kernel(
    const float* __restrict__ src, __nv_bfloat16* __restrict__ hi,
    __nv_bfloat16* __restrict__ lo, long long n4)
{
    long long i = (long long)blockIdx.x * 256 + threadIdx.x;
    if (i >= n4) return;
    float4 v = *(const float4*)(src + i * 4);
    __nv_bfloat16 h0, l0, h1, l1, h2, l2, h3, l3;
    split_bf16(v.x, h0, l0);
    split_bf16(v.y, h1, l1);
    split_bf16(v.z, h2, l2);
    split_bf16(v.w, h3, l3);
    __nv_bfloat162* hp = (__nv_bfloat162*)(hi + i * 4);
    __nv_bfloat162* lp = (__nv_bfloat162*)(lo + i * 4);
    __nv_bfloat162 a; a.x = h0; a.y = h1;
    __nv_bfloat162 b; b.x = h2; b.y = h3;
    __nv_bfloat162 c; c.x = l0; c.y = l1;
    __nv_bfloat162 d; d.x = l2; d.y = l3;
    hp[0] = a; hp[1] = b;
    lp[0] = c; lp[1] = d;
}

// ---------------- RoPE + RMSNorm + QKV split (writes hi/lo bf16) ----------------
// grid: (48 head-slots, S, B), block: 128. hh = kv*6 + slot; slot 0..3=q, 4=k, 5=v
__global__ __launch_bounds__(128) void rope_norm_kernel(
    const float* __restrict__ cosp, const float* __restrict__ sinp,
    const float* __restrict__ qw, const float* __restrict__ kw)
{
    int d = threadIdx.x;
    int hh = blockIdx.x;
    int s = blockIdx.y;
    int b = blockIdx.z;
    int kv = hh / 6;
    int slot = hh % 6;

    const float* row = g_qkv + ((size_t)(b * SS + s)) * QKVN + (size_t)hh * HD;
    float x = row[d];
    float out;

    __shared__ float red[HD];

    if (slot < 5) {
        float c = cosp[(size_t)s * HD + d];
        float sn = sinp[(size_t)s * HD + d];
        float other = row[d < 64 ? d + 64 : d - 64];
        float rot = (d < 64) ? -other : other;
        out = x * c + rot * sn;
        red[d] = out * out;
        __syncthreads();
#pragma unroll
        for (int off = 64; off > 0; off >>= 1) {
            if (d < off) red[d] += red[d + off];
            __syncthreads();
        }
        float inv = rsqrtf(red[0] / 128.0f + 1e-5f);
        const float* w = (slot < 4) ? qw : kw;
        out = w[d] * (out * inv);
    } else {
        out = x;  // v: plain copy
    }

    __nv_bfloat16 h, l;
    split_bf16(out, h, l);

    if (slot < 4) {
        int hq = kv * 4 + slot;
        size_t idx = (((size_t)(b * NH + hq)) * SS + s) * HD + d;
        g_qh[idx] = h; g_ql[idx] = l;
    } else if (slot == 4) {
        size_t idx = (((size_t)(b * HKV + kv)) * SS + s) * HD + d;
        g_kh[idx] = h; g_kl[idx] = l;
    } else {
        size_t idx = (((size_t)(b * HKV + kv)) * HD + d) * SS + s;   // transposed
        g_vth[idx] = h; g_vtl[idx] = l;
    }
}

// ---------------- row softmax over S=2048 -> bf16 hi/lo probs ----------------
__global__ __launch_bounds__(256) void softmax_kernel()
{
    size_t rowIdx = blockIdx.x;
    const float* x = g_scores + rowIdx * (size_t)SS;
    __nv_bfloat16* ph = g_ph + rowIdx * (size_t)SS;
    __nv_bfloat16* pl = g_pl + rowIdx * (size_t)SS;
    int t = threadIdx.x;

    float v[8];
    float m = -INFINITY;
#pragma unroll
    for (int i = 0; i < 8; i++) {
        v[i] = x[t + i * 256];
        m = fmaxf(m, v[i]);
    }

    __shared__ float red[256];
    red[t] = m;
    __syncthreads();
#pragma unroll
    for (int off = 128; off > 0; off >>= 1) {
        if (t < off) red[t] = fmaxf(red[t], red[t + off]);
        __syncthreads();
    }
    m = red[0];
    __syncthreads();

    float sum = 0.0f;
#pragma unroll
    for (int i = 0; i < 8; i++) {
        v[i] = expf(v[i] - m);
        sum += v[i];
    }
    red[t] = sum;
    __syncthreads();
#pragma unroll
    for (int off = 128; off > 0; off >>= 1) {
        if (t < off) red[t] += red[t + off];
        __syncthreads();
    }
    float inv = 1.0f / red[0];
#pragma unroll
    for (int i = 0; i < 8; i++) {
        float p = v[i] * inv;
        __nv_bfloat16 h, l;
        split_bf16(p, h, l);
        ph[t + i * 256] = h;
        pl[t + i * 256] = l;
    }
}

// ---------------- launcher ----------------
extern "C" void kernel_launch(void* const* d_in, const int* in_sizes, int n_in,
                              void* d_out, int out_size)
{
    (void)in_sizes; (void)n_in; (void)out_size;
    const float* hidden = (const float*)d_in[0];  // [B,S,D]
    const float* cosp   = (const float*)d_in[1];  // [1,S,128]
    const float* sinp   = (const float*)d_in[2];  // [1,S,128]
    const float* w_qkv  = (const float*)d_in[3];  // [6144,4096]
    const float* w_o    = (const float*)d_in[4];  // [4096,4096]
    const float* qnw    = (const float*)d_in[5];  // [128]
    const float* knw    = (const float*)d_in[6];  // [128]
    float* out = (float*)d_out;                   // [B,S,D]

    float *p_qkv, *p_sc;
    __nv_bfloat16 *p_hh, *p_hl, *p_wqh, *p_wql, *p_woh, *p_wol;
    __nv_bfloat16 *p_qhh, *p_qll, *p_kh, *p_kl, *p_vth, *p_vtl, *p_ph, *p_pl, *p_ah, *p_al;
    cudaGetSymbolAddress((void**)&p_qkv, g_qkv);
    cudaGetSymbolAddress((void**)&p_sc,  g_scores);
    cudaGetSymbolAddress((void**)&p_hh,  g_hh);
    cudaGetSymbolAddress((void**)&p_hl,  g_hl);
    cudaGetSymbolAddress((void**)&p_wqh, g_wqh);
    cudaGetSymbolAddress((void**)&p_wql, g_wql);
    cudaGetSymbolAddress((void**)&p_woh, g_woh);
    cudaGetSymbolAddress((void**)&p_wol, g_wol);
    cudaGetSymbolAddress((void**)&p_qhh, g_qh);
    cudaGetSymbolAddress((void**)&p_qll, g_ql);
    cudaGetSymbolAddress((void**)&p_kh,  g_kh);
    cudaGetSymbolAddress((void**)&p_kl,  g_kl);
    cudaGetSymbolAddress((void**)&p_vth, g_vth);
    cudaGetSymbolAddress((void**)&p_vtl, g_vtl);
    cudaGetSymbolAddress((void**)&p_ph,  g_ph);
    cudaGetSymbolAddress((void**)&p_pl,  g_pl);
    cudaGetSymbolAddress((void**)&p_ah,  g_ah);
    cudaGetSymbolAddress((void**)&p_al,  g_al);

    cudaFuncSetAttribute(tc_gemm, cudaFuncAttributeMaxDynamicSharedMemorySize, SM_TOTAL);

    const float scale = 0.08838834764831843f;  // 1/sqrt(128)

    // 0) split fp32 inputs into bf16 hi/lo
    long long nh4 = (long long)BB * SS * DD / 4;
    long long nq4 = (long long)QKVN * DD / 4;
    long long no4 = (long long)DD * DD / 4;
    split_kernel<<<(unsigned)((nh4 + 255) / 256), 256>>>(hidden, p_hh, p_hl, nh4);
    split_kernel<<<(unsigned)((nq4 + 255) / 256), 256>>>(w_qkv, p_wqh, p_wql, nq4);
    split_kernel<<<(unsigned)((no4 + 255) / 256), 256>>>(w_o, p_woh, p_wol, no4);

    // 1) qkv = hidden @ w_qkv^T   [4096, 6144] fp32
    tc_gemm<<<dim3(QKVN / 128, (BB * SS) / 128, 1), 256, SM_TOTAL>>>(
        p_hh, p_hl, p_wqh, p_wql, p_qkv, nullptr, nullptr,
        DD, DD, DD, QKVN, 0, 0, 0, 1.0f, 0, 0);

    // 2) RoPE + RMSNorm + split (q/k/vt hi+lo)
    rope_norm_kernel<<<dim3(HKV * 6, SS, BB), 128>>>(cosp, sinp, qnw, knw);

    // 3) scores = scale * Q @ K^T (fp32), batched z = b*32+h, GQA K
    tc_gemm<<<dim3(SS / 128, SS / 128, BB * NH), 256, SM_TOTAL>>>(
        p_qhh, p_qll, p_kh, p_kl, p_sc, nullptr, nullptr,
        HD, HD, HD, SS,
        (long long)SS * HD, (long long)SS * HD, (long long)SS * SS,
        scale, 1, 0);

    // 4) softmax -> P hi/lo bf16
    softmax_kernel<<<dim3(BB * NH * SS), 256>>>();

    // 5) attn = P @ Vt^T -> bf16 hi/lo at [B,S,32,HD]
    tc_gemm<<<dim3(1, SS / 128, BB * NH), 256, SM_TOTAL>>>(
        p_ph, p_pl, p_vth, p_vtl, nullptr, p_ah, p_al,
        SS, SS, SS, DD,
        (long long)SS * SS, (long long)HD * SS, 0,
        1.0f, 1, 1);

    // 6) out = attn @ w_o^T (fp32)
    tc_gemm<<<dim3(DD / 128, (BB * SS) / 128, 1), 256, SM_TOTAL>>>(
        p_ah, p_al, p_woh, p_wol, out, nullptr, nullptr,
        DD, DD, DD, DD, 0, 0, 0, 1.0f, 0, 0);
}